// round 5
// baseline (speedup 1.0000x reference)
#include <cuda_runtime.h>

#define BB 4
#define FF 32
#define CC 4096
#define TT 32
#define EE 65536
#define KK 9
#define NSEG 1024               // T*F floats per (b,c) tile
#define NTOT (BB*FF*CC*TT)      // 16777216

// ---------------- scratch (device globals; no allocs allowed) ----------------
__device__ float g_deg[CC];
__device__ float g_dis[CC];
__device__ int   g_cnt[CC];
__device__ int   g_off[CC + 1];
__device__ int   g_pos[CC];
__device__ int   g_eid[EE];
__device__ float g_norm[EE];
__device__ float g_buf0[NTOT];   // x_lin
__device__ float g_buf1[NTOT];   // h1 (gcn pre-norm) -> overwritten in-place by conv out
__device__ float g_s1[BB*FF], g_q1[BB*FF], g_s2[BB*FF], g_q2[BB*FF];
__device__ float g_mu1[BB*FF], g_rs1[BB*FF], g_mu2[BB*FF], g_rs2[BB*FF];

// ---------------- packed f32x2 helpers ----------------
__device__ __forceinline__ unsigned long long pack2(float x, float y) {
    unsigned long long r;
    asm("mov.b64 %0, {%1,%2};" : "=l"(r) : "f"(x), "f"(y));
    return r;
}
__device__ __forceinline__ void unpack2(unsigned long long v, float& x, float& y) {
    asm("mov.b64 {%0,%1}, %2;" : "=f"(x), "=f"(y) : "l"(v));
}
__device__ __forceinline__ unsigned long long fma2(unsigned long long a,
                                                   unsigned long long b,
                                                   unsigned long long c) {
    unsigned long long d;
    asm("fma.rn.f32x2 %0, %1, %2, %3;" : "=l"(d) : "l"(a), "l"(b), "l"(c));
    return d;
}

// ---------------- 1: init ----------------
__global__ void k_prep() {
    int i = blockIdx.x * blockDim.x + threadIdx.x;
    if (i < CC) { g_deg[i] = 1.0f; g_cnt[i] = 0; }
    if (i < BB*FF) { g_s1[i] = 0.f; g_q1[i] = 0.f; g_s2[i] = 0.f; g_q2[i] = 0.f; }
}

// ---------------- 2: degree + bucket counts ----------------
__global__ void k_edge1(const int* __restrict__ ei, const float* __restrict__ ew) {
    int e = blockIdx.x * blockDim.x + threadIdx.x;
    if (e < EE) {
        int d = ei[EE + e];
        atomicAdd(&g_deg[d], ew[e]);
        atomicAdd(&g_cnt[d], 1);
    }
}

// ---------------- 3: prefix scan (CSR offsets) + dis ----------------
__global__ void k_scan() {
    __shared__ int s[1024];
    int tid = threadIdx.x;
    int c0 = tid * 4;
    int l0 = g_cnt[c0], l1 = g_cnt[c0+1], l2 = g_cnt[c0+2], l3 = g_cnt[c0+3];
    int tot = l0 + l1 + l2 + l3;
    s[tid] = tot;
    __syncthreads();
    for (int d = 1; d < 1024; d <<= 1) {
        int v = 0;
        if (tid >= d) v = s[tid - d];
        __syncthreads();
        if (tid >= d) s[tid] += v;
        __syncthreads();
    }
    int excl = s[tid] - tot;
    g_off[c0]   = excl;              g_pos[c0]   = excl;
    g_off[c0+1] = excl + l0;         g_pos[c0+1] = excl + l0;
    g_off[c0+2] = excl + l0 + l1;    g_pos[c0+2] = excl + l0 + l1;
    g_off[c0+3] = excl + l0 + l1 + l2; g_pos[c0+3] = excl + l0 + l1 + l2;
    if (tid == 1023) g_off[CC] = s[1023];
    g_dis[c0]   = rsqrtf(g_deg[c0]);
    g_dis[c0+1] = rsqrtf(g_deg[c0+1]);
    g_dis[c0+2] = rsqrtf(g_deg[c0+2]);
    g_dis[c0+3] = rsqrtf(g_deg[c0+3]);
}

// ---------------- 4: fill CSR + edge norms ----------------
__global__ void k_edge2(const int* __restrict__ ei, const float* __restrict__ ew) {
    int e = blockIdx.x * blockDim.x + threadIdx.x;
    if (e < EE) {
        int sN = ei[e];
        int d  = ei[EE + e];
        int slot = atomicAdd(&g_pos[d], 1);
        g_eid[slot] = e;
        g_norm[e] = g_dis[sN] * ew[e] * g_dis[d];
    }
}

// ---------------- 5: x_lin[b,c,t,g] = sum_f x[b,f,c,t] * W[f,g] ----------------
__global__ void k_xlin(const float* __restrict__ x, const float* __restrict__ W) {
    __shared__ float xs[32 * 33];
    __shared__ float ws[1024];
    int tid = threadIdx.x;
    int bc = blockIdx.x;
    int b = bc >> 12, c = bc & (CC - 1);
    int lf = tid >> 5, lt = tid & 31;
    xs[lt * 33 + lf] = x[(((size_t)b * FF + lf) * CC + c) * TT + lt];
    ws[tid] = W[tid];
    __syncthreads();
    int g = tid & 31, t = tid >> 5;
    float wreg[32];
#pragma unroll
    for (int f = 0; f < 32; ++f) wreg[f] = ws[f * 32 + g];
    float acc = 0.f;
#pragma unroll
    for (int f = 0; f < 32; ++f) acc += xs[t * 33 + f] * wreg[f];
    g_buf0[((size_t)b * CC + c) * NSEG + tid] = acc;
}

// ---------------- 6: aggregate (gather form) + bias + stats1 ----------------
__global__ void k_agg(const int* __restrict__ ei, const float* __restrict__ gcnb) {
    __shared__ int   s_src[256];
    __shared__ float s_nrm[256];
    __shared__ float sred[1024];
    int tid = threadIdx.x;
    int bc = blockIdx.x;
    int b = bc >> 12, c = bc & (CC - 1);
    size_t base = ((size_t)b * CC + c) * NSEG;
    float ds = g_dis[c];
    float acc = g_buf0[base + tid] * (ds * ds);        // self-loop term
    int beg = g_off[c], end = g_off[c + 1];
    for (int j0 = beg; j0 < end; j0 += 256) {
        int n = min(256, end - j0);
        __syncthreads();
        if (tid < n) {
            int e = g_eid[j0 + tid];
            s_src[tid] = ei[e];
            s_nrm[tid] = g_norm[e];
        }
        __syncthreads();
        int j = 0;
        for (; j + 4 <= n; j += 4) {
            float v0 = g_buf0[((size_t)b * CC + s_src[j    ]) * NSEG + tid];
            float v1 = g_buf0[((size_t)b * CC + s_src[j + 1]) * NSEG + tid];
            float v2 = g_buf0[((size_t)b * CC + s_src[j + 2]) * NSEG + tid];
            float v3 = g_buf0[((size_t)b * CC + s_src[j + 3]) * NSEG + tid];
            acc += v0 * s_nrm[j];
            acc += v1 * s_nrm[j + 1];
            acc += v2 * s_nrm[j + 2];
            acc += v3 * s_nrm[j + 3];
        }
        for (; j < n; ++j)
            acc += g_buf0[((size_t)b * CC + s_src[j]) * NSEG + tid] * s_nrm[j];
    }
    int g = tid & 31;
    acc += gcnb[g];
    g_buf1[base + tid] = acc;
    // per-(b,g) partial stats
    __syncthreads();
    sred[tid] = acc;
    __syncthreads();
#pragma unroll
    for (int st = 512; st >= 32; st >>= 1) {
        if (tid < st) sred[tid] += sred[tid + st];
        __syncthreads();
    }
    if (tid < 32) atomicAdd(&g_s1[b * 32 + tid], sred[tid]);
    __syncthreads();
    sred[tid] = acc * acc;
    __syncthreads();
#pragma unroll
    for (int st = 512; st >= 32; st >>= 1) {
        if (tid < st) sred[tid] += sred[tid + st];
        __syncthreads();
    }
    if (tid < 32) atomicAdd(&g_q1[b * 32 + tid], sred[tid]);
}

// ---------------- 7/10: finalize stats ----------------
__global__ void k_fin(int stage) {
    int i = threadIdx.x;
    if (i < BB * FF) {
        const float invN = 1.0f / (float)(CC * TT);
        float s = stage ? g_s2[i] : g_s1[i];
        float q = stage ? g_q2[i] : g_q1[i];
        float m = s * invN;
        float v = q * invN - m * m;
        float r = rsqrtf(v + 1e-5f);
        if (stage) { g_mu2[i] = m; g_rs2[i] = r; }
        else       { g_mu1[i] = m; g_rs1[i] = r; }
    }
}

// ---------------- 8: fused IN1+ReLU + temporal conv (1xK) + bias + stats2 ----
// 256 threads = 4 (b,c) tiles of 64 threads. Thread computes 4t x 4o via
// packed fma.rn.f32x2 (two f32x2 accumulator pairs per t).
// Reads h1 from g_buf1, applies IN1+ReLU on load, writes conv out back
// in-place to g_buf1 (block touches only its own tile; sync in between).
// Dynamic smem layout:
//   ws : float [KK*1024]                    (36864 B)   [k][i][o]
//   zd : ull   [4][1280]  ({v,v} splats)    (40960 B)   [tile][(t+4)*32+i]
//   red2 aliases zd after compute.
__global__ void k_conv(const float* __restrict__ cw, const float* __restrict__ cb) {
    extern __shared__ char dsm[];
    float* ws = (float*)dsm;
    unsigned long long* zd = (unsigned long long*)(dsm + KK * 1024 * 4);
    int tid = threadIdx.x;
    int bc4 = blockIdx.x;                 // BB*CC/4
    int b = bc4 >> 10;
    int cquad = bc4 & 1023;
    int tile = tid >> 6;
    int r = tid & 63;
    int c = cquad * 4 + tile;

    // load weights [k][i][o]
    for (int idx = tid; idx < KK * 1024; idx += 256) {
        int k = idx >> 10;
        int rem = idx & 1023;
        int i = rem >> 5, o = rem & 31;
        ws[idx] = cw[(o * 32 + i) * KK + k];
    }

    // load z tile with IN1+ReLU fused, store duplicated {v,v}
    size_t base = ((size_t)b * CC + c) * NSEG;
    {
        int g = r & 31;
        float mu = g_mu1[b * 32 + g];
        float rs = g_rs1[b * 32 + g];
        unsigned long long* zt = zd + tile * 1280;
        for (int idx = r; idx < 1280; idx += 64) {
            int row = idx >> 5;
            float v = 0.f;
            if (row >= 4 && row < 36) {
                float h = g_buf1[base + (row - 4) * 32 + (idx & 31)];
                v = fmaxf(0.f, (h - mu) * rs);
            }
            zt[idx] = pack2(v, v);
        }
    }
    __syncthreads();

    int o0 = (r & 7) * 4;                 // 8 o-groups of 4
    int tb = (r >> 3) * 4;                // 8 t-blocks of 4
    float b0 = cb[o0], b1 = cb[o0 + 1], b2 = cb[o0 + 2], b3 = cb[o0 + 3];
    unsigned long long acc[4][2];
#pragma unroll
    for (int t = 0; t < 4; ++t) { acc[t][0] = pack2(b0, b1); acc[t][1] = pack2(b2, b3); }

    const unsigned long long* zt = zd + tile * 1280;
#pragma unroll 1
    for (int k = 0; k < KK; ++k) {
        const float* wk = ws + k * 1024 + o0;
        const unsigned long long* zr = zt + (tb + k) * 32;
#pragma unroll
        for (int i = 0; i < 32; ++i) {
            float4 w4 = *(const float4*)(wk + i * 32);
            unsigned long long wlo = pack2(w4.x, w4.y);
            unsigned long long whi = pack2(w4.z, w4.w);
            unsigned long long z0 = zr[i];
            unsigned long long z1 = zr[32 + i];
            unsigned long long z2 = zr[64 + i];
            unsigned long long z3 = zr[96 + i];
            acc[0][0] = fma2(z0, wlo, acc[0][0]); acc[0][1] = fma2(z0, whi, acc[0][1]);
            acc[1][0] = fma2(z1, wlo, acc[1][0]); acc[1][1] = fma2(z1, whi, acc[1][1]);
            acc[2][0] = fma2(z2, wlo, acc[2][0]); acc[2][1] = fma2(z2, whi, acc[2][1]);
            acc[3][0] = fma2(z3, wlo, acc[3][0]); acc[3][1] = fma2(z3, whi, acc[3][1]);
        }
    }

    // unpack, store (in-place), and accumulate per-o stats
    float av[4][4];
    float p[4] = {0.f, 0.f, 0.f, 0.f};
    float q[4] = {0.f, 0.f, 0.f, 0.f};
#pragma unroll
    for (int t = 0; t < 4; ++t) {
        unpack2(acc[t][0], av[t][0], av[t][1]);
        unpack2(acc[t][1], av[t][2], av[t][3]);
#pragma unroll
        for (int oo = 0; oo < 4; ++oo) {
            p[oo] += av[t][oo];
            q[oo] += av[t][oo] * av[t][oo];
        }
        float4 st = make_float4(av[t][0], av[t][1], av[t][2], av[t][3]);
        *(float4*)&g_buf1[base + (size_t)(tb + t) * 32 + o0] = st;
    }

    // stats2 reduction: threads with same (tid & 7) share the same o-group
    float2* red2 = (float2*)(dsm + KK * 1024 * 4);
#pragma unroll
    for (int oo = 0; oo < 4; ++oo) {
        __syncthreads();
        red2[tid] = make_float2(p[oo], q[oo]);
        __syncthreads();
#pragma unroll
        for (int st = 128; st >= 8; st >>= 1) {
            if (tid < st) {
                red2[tid].x += red2[tid + st].x;
                red2[tid].y += red2[tid + st].y;
            }
            __syncthreads();
        }
        if (tid < 8) {
            atomicAdd(&g_s2[b * 32 + tid * 4 + oo], red2[tid].x);
            atomicAdd(&g_q2[b * 32 + tid * 4 + oo], red2[tid].y);
        }
    }
}

// ---------------- 11: IN2 + ReLU + residual + ReLU + transpose ----------------
__global__ void k_final(const float* __restrict__ x, float* __restrict__ out) {
    __shared__ float sy[32 * 33];
    int tid = threadIdx.x;
    int bc = blockIdx.x;
    int b = bc >> 12, c = bc & (CC - 1);
    size_t base = ((size_t)b * CC + c) * NSEG;
    int o = tid & 31, t = tid >> 5;
    float v = g_buf1[base + tid];
    v = fmaxf(0.f, (v - g_mu2[b * 32 + o]) * g_rs2[b * 32 + o]);
    sy[t * 33 + o] = v;
    __syncthreads();
    int f = tid >> 5, t2 = tid & 31;
    size_t xi = (((size_t)b * FF + f) * CC + c) * TT + t2;
    out[xi] = fmaxf(0.f, sy[t2 * 33 + f] + x[xi]);
}

// ---------------- launch ----------------
extern "C" void kernel_launch(void* const* d_in, const int* in_sizes, int n_in,
                              void* d_out, int out_size) {
    const float* x    = (const float*)d_in[0];
    const int*   ei   = (const int*)d_in[1];
    const float* ew   = (const float*)d_in[2];
    const float* W    = (const float*)d_in[3];
    const float* gcnb = (const float*)d_in[4];
    const float* cw   = (const float*)d_in[5];
    const float* cb   = (const float*)d_in[6];
    float* out = (float*)d_out;

    const int conv_smem = KK * 1024 * 4 + 4 * 1280 * 8;   // 36864 + 40960 = 77824
    cudaFuncSetAttribute(k_conv, cudaFuncAttributeMaxDynamicSharedMemorySize, conv_smem);

    k_prep <<<16, 256>>>();
    k_edge1<<<EE / 256, 256>>>(ei, ew);
    k_scan <<<1, 1024>>>();
    k_edge2<<<EE / 256, 256>>>(ei, ew);
    k_xlin <<<BB * CC, 1024>>>(x, W);
    k_agg  <<<BB * CC, 1024>>>(ei, gcnb);
    k_fin  <<<1, 128>>>(0);
    k_conv <<<BB * CC / 4, 256, conv_smem>>>(cw, cb);
    k_fin  <<<1, 128>>>(1);
    k_final<<<BB * CC, 1024>>>(x, out);
}

// round 6
// speedup vs baseline: 1.3648x; 1.3648x over previous
#include <cuda_runtime.h>

#define BB 4
#define FF 32
#define CC 4096
#define TT 32
#define EE 65536
#define KK 9
#define NSEG 1024               // T*F floats per (b,c) tile
#define NTOT (BB*FF*CC*TT)      // 16777216

// ---------------- scratch (device globals; no allocs allowed) ----------------
__device__ float g_deg[CC];
__device__ float g_dis[CC];
__device__ int   g_cnt[CC];
__device__ int   g_off[CC + 1];
__device__ int   g_pos[CC];
__device__ int   g_srcS[EE];     // CSR-sorted source node per slot
__device__ float g_nrmS[EE];     // CSR-sorted edge norm per slot
__device__ float g_buf0[NTOT];   // x_lin
__device__ float g_buf1[NTOT];   // h1 -> overwritten in-place by conv out
__device__ float g_s1[BB*FF], g_q1[BB*FF], g_s2[BB*FF], g_q2[BB*FF];
__device__ float g_mu1[BB*FF], g_rs1[BB*FF], g_mu2[BB*FF], g_rs2[BB*FF];

// ---------------- packed f32x2 helpers ----------------
__device__ __forceinline__ unsigned long long pack2(float x, float y) {
    unsigned long long r;
    asm("mov.b64 %0, {%1,%2};" : "=l"(r) : "f"(x), "f"(y));
    return r;
}
__device__ __forceinline__ void unpack2(unsigned long long v, float& x, float& y) {
    asm("mov.b64 {%0,%1}, %2;" : "=f"(x), "=f"(y) : "l"(v));
}
__device__ __forceinline__ unsigned long long fma2(unsigned long long a,
                                                   unsigned long long b,
                                                   unsigned long long c) {
    unsigned long long d;
    asm("fma.rn.f32x2 %0, %1, %2, %3;" : "=l"(d) : "l"(a), "l"(b), "l"(c));
    return d;
}

// ---------------- 1: init ----------------
__global__ void k_prep() {
    int i = blockIdx.x * blockDim.x + threadIdx.x;
    if (i < CC) { g_deg[i] = 1.0f; g_cnt[i] = 0; }
    if (i < BB*FF) { g_s1[i] = 0.f; g_q1[i] = 0.f; g_s2[i] = 0.f; g_q2[i] = 0.f; }
}

// ---------------- 2: degree + bucket counts ----------------
__global__ void k_edge1(const int* __restrict__ ei, const float* __restrict__ ew) {
    int e = blockIdx.x * blockDim.x + threadIdx.x;
    if (e < EE) {
        int d = ei[EE + e];
        atomicAdd(&g_deg[d], ew[e]);
        atomicAdd(&g_cnt[d], 1);
    }
}

// ---------------- 3: prefix scan (CSR offsets) + dis ----------------
__global__ void k_scan() {
    __shared__ int s[1024];
    int tid = threadIdx.x;
    int c0 = tid * 4;
    int l0 = g_cnt[c0], l1 = g_cnt[c0+1], l2 = g_cnt[c0+2], l3 = g_cnt[c0+3];
    int tot = l0 + l1 + l2 + l3;
    s[tid] = tot;
    __syncthreads();
    for (int d = 1; d < 1024; d <<= 1) {
        int v = 0;
        if (tid >= d) v = s[tid - d];
        __syncthreads();
        if (tid >= d) s[tid] += v;
        __syncthreads();
    }
    int excl = s[tid] - tot;
    g_off[c0]   = excl;              g_pos[c0]   = excl;
    g_off[c0+1] = excl + l0;         g_pos[c0+1] = excl + l0;
    g_off[c0+2] = excl + l0 + l1;    g_pos[c0+2] = excl + l0 + l1;
    g_off[c0+3] = excl + l0 + l1 + l2; g_pos[c0+3] = excl + l0 + l1 + l2;
    if (tid == 1023) g_off[CC] = s[1023];
    g_dis[c0]   = rsqrtf(g_deg[c0]);
    g_dis[c0+1] = rsqrtf(g_deg[c0+1]);
    g_dis[c0+2] = rsqrtf(g_deg[c0+2]);
    g_dis[c0+3] = rsqrtf(g_deg[c0+3]);
}

// ---------------- 4: fill sorted CSR arrays (src, norm) ----------------
__global__ void k_edge2(const int* __restrict__ ei, const float* __restrict__ ew) {
    int e = blockIdx.x * blockDim.x + threadIdx.x;
    if (e < EE) {
        int sN = ei[e];
        int d  = ei[EE + e];
        int slot = atomicAdd(&g_pos[d], 1);
        g_srcS[slot] = sN;
        g_nrmS[slot] = g_dis[sN] * ew[e] * g_dis[d];
    }
}

// ---------------- 5: x_lin[b,c,t,g] = sum_f x[b,f,c,t] * W[f,g] ----------------
// 256 threads; thread owns (t = tid>>3, g0 = (tid&7)*4) -> tile element tid*4.
__global__ void k_xlin(const float* __restrict__ x, const float* __restrict__ W) {
    __shared__ float xs[32 * 33];
    __shared__ float ws[1024];          // [f][g]
    int tid = threadIdx.x;
    int bc = blockIdx.x;
    int b = bc >> 12, c = bc & (CC - 1);
    ((float4*)ws)[tid] = ((const float4*)W)[tid];
    int lf = tid >> 3, lt0 = (tid & 7) * 4;
    float4 xv = *(const float4*)&x[(((size_t)b * FF + lf) * CC + c) * TT + lt0];
    xs[(lt0 + 0) * 33 + lf] = xv.x;
    xs[(lt0 + 1) * 33 + lf] = xv.y;
    xs[(lt0 + 2) * 33 + lf] = xv.z;
    xs[(lt0 + 3) * 33 + lf] = xv.w;
    __syncthreads();
    int t = tid >> 3, g0 = (tid & 7) * 4;
    unsigned long long a0 = pack2(0.f, 0.f), a1 = pack2(0.f, 0.f);
#pragma unroll
    for (int f = 0; f < 32; ++f) {
        float z = xs[t * 33 + f];
        unsigned long long zz = pack2(z, z);
        float4 w4 = *(const float4*)&ws[f * 32 + g0];
        a0 = fma2(zz, pack2(w4.x, w4.y), a0);
        a1 = fma2(zz, pack2(w4.z, w4.w), a1);
    }
    float4 o;
    unpack2(a0, o.x, o.y);
    unpack2(a1, o.z, o.w);
    *(float4*)&g_buf0[((size_t)b * CC + c) * NSEG + (size_t)tid * 4] = o;
}

// ---------------- 6: aggregate (gather, all 4 batches per block) + stats1 ----
// 256 threads, 1 block per node c. Thread owns float4 at tile offset tid*4
// for each of the 4 batches. Per 2-edge step: 8 independent LDG.128 in flight.
__global__ void k_agg(const float* __restrict__ gcnb) {
    __shared__ int    s_src[64];
    __shared__ float  s_nrm[64];
    __shared__ float4 sP[64];           // [warp][group]
    __shared__ float4 sQ[64];
    int tid = threadIdx.x;
    int c = blockIdx.x;
    int off = tid * 4;
    float ds = g_dis[c];
    float d2 = ds * ds;
    float4 acc[BB];
#pragma unroll
    for (int b = 0; b < BB; ++b) {
        float4 v = *(const float4*)&g_buf0[((size_t)b * CC + c) * NSEG + off];
        acc[b] = make_float4(v.x * d2, v.y * d2, v.z * d2, v.w * d2);
    }
    int beg = g_off[c], end = g_off[c + 1];
    for (int j0 = beg; j0 < end; j0 += 64) {
        int n = min(64, end - j0);
        __syncthreads();
        if (tid < n) {
            s_src[tid] = g_srcS[j0 + tid];
            s_nrm[tid] = g_nrmS[j0 + tid];
        }
        __syncthreads();
        int j = 0;
        for (; j + 2 <= n; j += 2) {
            int s0 = s_src[j], s1 = s_src[j + 1];
            float n0 = s_nrm[j], n1 = s_nrm[j + 1];
            float4 v[2 * BB];
#pragma unroll
            for (int b = 0; b < BB; ++b) {
                v[b]      = *(const float4*)&g_buf0[((size_t)b * CC + s0) * NSEG + off];
                v[BB + b] = *(const float4*)&g_buf0[((size_t)b * CC + s1) * NSEG + off];
            }
#pragma unroll
            for (int b = 0; b < BB; ++b) {
                acc[b].x += v[b].x * n0; acc[b].y += v[b].y * n0;
                acc[b].z += v[b].z * n0; acc[b].w += v[b].w * n0;
                acc[b].x += v[BB+b].x * n1; acc[b].y += v[BB+b].y * n1;
                acc[b].z += v[BB+b].z * n1; acc[b].w += v[BB+b].w * n1;
            }
        }
        if (j < n) {
            int s0 = s_src[j];
            float n0 = s_nrm[j];
#pragma unroll
            for (int b = 0; b < BB; ++b) {
                float4 v = *(const float4*)&g_buf0[((size_t)b * CC + s0) * NSEG + off];
                acc[b].x += v.x * n0; acc[b].y += v.y * n0;
                acc[b].z += v.z * n0; acc[b].w += v.w * n0;
            }
        }
    }
    int g0 = off & 31;                  // (tid&7)*4
    float4 bias = *(const float4*)&gcnb[g0];
    int warp = tid >> 5, lane = tid & 31;
#pragma unroll
    for (int b = 0; b < BB; ++b) {
        acc[b].x += bias.x; acc[b].y += bias.y;
        acc[b].z += bias.z; acc[b].w += bias.w;
        *(float4*)&g_buf1[((size_t)b * CC + c) * NSEG + off] = acc[b];
        // stats: reduce p,q over threads sharing g0 (lanes l, l^8, l^16 in warp,
        // then across 8 warps via smem)
        float4 p = acc[b];
        float4 q = make_float4(p.x*p.x, p.y*p.y, p.z*p.z, p.w*p.w);
#pragma unroll
        for (int m = 8; m <= 16; m <<= 1) {
            p.x += __shfl_xor_sync(0xffffffff, p.x, m);
            p.y += __shfl_xor_sync(0xffffffff, p.y, m);
            p.z += __shfl_xor_sync(0xffffffff, p.z, m);
            p.w += __shfl_xor_sync(0xffffffff, p.w, m);
            q.x += __shfl_xor_sync(0xffffffff, q.x, m);
            q.y += __shfl_xor_sync(0xffffffff, q.y, m);
            q.z += __shfl_xor_sync(0xffffffff, q.z, m);
            q.w += __shfl_xor_sync(0xffffffff, q.w, m);
        }
        if (lane < 8) { sP[warp * 8 + lane] = p; sQ[warp * 8 + lane] = q; }
        __syncthreads();
        if (tid < 8) {
            float4 tp = sP[tid], tq = sQ[tid];
#pragma unroll
            for (int w = 1; w < 8; ++w) {
                float4 ap = sP[w * 8 + tid], aq = sQ[w * 8 + tid];
                tp.x += ap.x; tp.y += ap.y; tp.z += ap.z; tp.w += ap.w;
                tq.x += aq.x; tq.y += aq.y; tq.z += aq.z; tq.w += aq.w;
            }
            int base = b * 32 + tid * 4;
            atomicAdd(&g_s1[base + 0], tp.x); atomicAdd(&g_s1[base + 1], tp.y);
            atomicAdd(&g_s1[base + 2], tp.z); atomicAdd(&g_s1[base + 3], tp.w);
            atomicAdd(&g_q1[base + 0], tq.x); atomicAdd(&g_q1[base + 1], tq.y);
            atomicAdd(&g_q1[base + 2], tq.z); atomicAdd(&g_q1[base + 3], tq.w);
        }
        __syncthreads();
    }
}

// ---------------- 7/10: finalize stats ----------------
__global__ void k_fin(int stage) {
    int i = threadIdx.x;
    if (i < BB * FF) {
        const float invN = 1.0f / (float)(CC * TT);
        float s = stage ? g_s2[i] : g_s1[i];
        float q = stage ? g_q2[i] : g_q1[i];
        float m = s * invN;
        float v = q * invN - m * m;
        float r = rsqrtf(v + 1e-5f);
        if (stage) { g_mu2[i] = m; g_rs2[i] = r; }
        else       { g_mu1[i] = m; g_rs1[i] = r; }
    }
}

// ---------------- 8: fused IN1+ReLU + temporal conv (1xK) + bias + stats2 ----
__global__ void k_conv(const float* __restrict__ cw, const float* __restrict__ cb) {
    extern __shared__ char dsm[];
    float* ws = (float*)dsm;
    unsigned long long* zd = (unsigned long long*)(dsm + KK * 1024 * 4);
    int tid = threadIdx.x;
    int bc4 = blockIdx.x;                 // BB*CC/4
    int b = bc4 >> 10;
    int cquad = bc4 & 1023;
    int tile = tid >> 6;
    int r = tid & 63;
    int c = cquad * 4 + tile;

    for (int idx = tid; idx < KK * 1024; idx += 256) {
        int k = idx >> 10;
        int rem = idx & 1023;
        int i = rem >> 5, o = rem & 31;
        ws[idx] = cw[(o * 32 + i) * KK + k];
    }

    size_t base = ((size_t)b * CC + c) * NSEG;
    {
        int g = r & 31;
        float mu = g_mu1[b * 32 + g];
        float rs = g_rs1[b * 32 + g];
        unsigned long long* zt = zd + tile * 1280;
        for (int idx = r; idx < 1280; idx += 64) {
            int row = idx >> 5;
            float v = 0.f;
            if (row >= 4 && row < 36) {
                float h = g_buf1[base + (row - 4) * 32 + (idx & 31)];
                v = fmaxf(0.f, (h - mu) * rs);
            }
            zt[idx] = pack2(v, v);
        }
    }
    __syncthreads();

    int o0 = (r & 7) * 4;
    int tb = (r >> 3) * 4;
    float b0 = cb[o0], b1 = cb[o0 + 1], b2 = cb[o0 + 2], b3 = cb[o0 + 3];
    unsigned long long acc[4][2];
#pragma unroll
    for (int t = 0; t < 4; ++t) { acc[t][0] = pack2(b0, b1); acc[t][1] = pack2(b2, b3); }

    const unsigned long long* zt = zd + tile * 1280;
#pragma unroll 1
    for (int k = 0; k < KK; ++k) {
        const float* wk = ws + k * 1024 + o0;
        const unsigned long long* zr = zt + (tb + k) * 32;
#pragma unroll
        for (int i = 0; i < 32; ++i) {
            float4 w4 = *(const float4*)(wk + i * 32);
            unsigned long long wlo = pack2(w4.x, w4.y);
            unsigned long long whi = pack2(w4.z, w4.w);
            unsigned long long z0 = zr[i];
            unsigned long long z1 = zr[32 + i];
            unsigned long long z2 = zr[64 + i];
            unsigned long long z3 = zr[96 + i];
            acc[0][0] = fma2(z0, wlo, acc[0][0]); acc[0][1] = fma2(z0, whi, acc[0][1]);
            acc[1][0] = fma2(z1, wlo, acc[1][0]); acc[1][1] = fma2(z1, whi, acc[1][1]);
            acc[2][0] = fma2(z2, wlo, acc[2][0]); acc[2][1] = fma2(z2, whi, acc[2][1]);
            acc[3][0] = fma2(z3, wlo, acc[3][0]); acc[3][1] = fma2(z3, whi, acc[3][1]);
        }
    }

    float av[4][4];
    float p[4] = {0.f, 0.f, 0.f, 0.f};
    float q[4] = {0.f, 0.f, 0.f, 0.f};
#pragma unroll
    for (int t = 0; t < 4; ++t) {
        unpack2(acc[t][0], av[t][0], av[t][1]);
        unpack2(acc[t][1], av[t][2], av[t][3]);
#pragma unroll
        for (int oo = 0; oo < 4; ++oo) {
            p[oo] += av[t][oo];
            q[oo] += av[t][oo] * av[t][oo];
        }
        float4 st = make_float4(av[t][0], av[t][1], av[t][2], av[t][3]);
        *(float4*)&g_buf1[base + (size_t)(tb + t) * 32 + o0] = st;
    }

    float2* red2 = (float2*)(dsm + KK * 1024 * 4);
#pragma unroll
    for (int oo = 0; oo < 4; ++oo) {
        __syncthreads();
        red2[tid] = make_float2(p[oo], q[oo]);
        __syncthreads();
#pragma unroll
        for (int st = 128; st >= 8; st >>= 1) {
            if (tid < st) {
                red2[tid].x += red2[tid + st].x;
                red2[tid].y += red2[tid + st].y;
            }
            __syncthreads();
        }
        if (tid < 8) {
            atomicAdd(&g_s2[b * 32 + tid * 4 + oo], red2[tid].x);
            atomicAdd(&g_q2[b * 32 + tid * 4 + oo], red2[tid].y);
        }
    }
}

// ---------------- 11: IN2 + ReLU + residual + ReLU + transpose ----------------
// 256 threads, float4 per thread on both sides of the transpose.
__global__ void k_final(const float* __restrict__ x, float* __restrict__ out) {
    __shared__ float sy[32 * 33];
    int tid = threadIdx.x;
    int bc = blockIdx.x;
    int b = bc >> 12, c = bc & (CC - 1);
    size_t base = ((size_t)b * CC + c) * NSEG;
    int t = tid >> 3, o0 = (tid & 7) * 4;
    float4 v = *(const float4*)&g_buf1[base + (size_t)tid * 4];
    float4 mu = *(const float4*)&g_mu2[b * 32 + o0];
    float4 rs = *(const float4*)&g_rs2[b * 32 + o0];
    sy[t * 33 + o0 + 0] = fmaxf(0.f, (v.x - mu.x) * rs.x);
    sy[t * 33 + o0 + 1] = fmaxf(0.f, (v.y - mu.y) * rs.y);
    sy[t * 33 + o0 + 2] = fmaxf(0.f, (v.z - mu.z) * rs.z);
    sy[t * 33 + o0 + 3] = fmaxf(0.f, (v.w - mu.w) * rs.w);
    __syncthreads();
    int f = tid >> 3, t0 = (tid & 7) * 4;
    size_t xi = (((size_t)b * FF + f) * CC + c) * TT + t0;
    float4 xv = *(const float4*)&x[xi];
    float4 o;
    o.x = fmaxf(0.f, sy[(t0 + 0) * 33 + f] + xv.x);
    o.y = fmaxf(0.f, sy[(t0 + 1) * 33 + f] + xv.y);
    o.z = fmaxf(0.f, sy[(t0 + 2) * 33 + f] + xv.z);
    o.w = fmaxf(0.f, sy[(t0 + 3) * 33 + f] + xv.w);
    *(float4*)&out[xi] = o;
}

// ---------------- launch ----------------
extern "C" void kernel_launch(void* const* d_in, const int* in_sizes, int n_in,
                              void* d_out, int out_size) {
    const float* x    = (const float*)d_in[0];
    const int*   ei   = (const int*)d_in[1];
    const float* ew   = (const float*)d_in[2];
    const float* W    = (const float*)d_in[3];
    const float* gcnb = (const float*)d_in[4];
    const float* cw   = (const float*)d_in[5];
    const float* cb   = (const float*)d_in[6];
    float* out = (float*)d_out;

    const int conv_smem = KK * 1024 * 4 + 4 * 1280 * 8;   // 77824
    cudaFuncSetAttribute(k_conv, cudaFuncAttributeMaxDynamicSharedMemorySize, conv_smem);

    k_prep <<<16, 256>>>();
    k_edge1<<<EE / 256, 256>>>(ei, ew);
    k_scan <<<1, 1024>>>();
    k_edge2<<<EE / 256, 256>>>(ei, ew);
    k_xlin <<<BB * CC, 256>>>(x, W);
    k_agg  <<<CC, 256>>>(gcnb);
    k_fin  <<<1, 128>>>(0);
    k_conv <<<BB * CC / 4, 256, conv_smem>>>(cw, cb);
    k_fin  <<<1, 128>>>(1);
    k_final<<<BB * CC, 256>>>(x, out);
}